// round 2
// baseline (speedup 1.0000x reference)
#include <cuda_runtime.h>

// Problem constants
#define B_  8
#define C_  256
#define H_  128
#define W_  128
#define N_ELEM (B_*C_*H_*W_)   // 33,554,432 floats = 134.2 MB

// Scratch buffers (no cudaMalloc allowed)
__device__ float g_b0[N_ELEM];
__device__ float g_b1[N_ELEM];
__device__ float g_b2[N_ELEM];

// ---------- packed f32x2 helpers (sm_103a FFMA2 path) ----------
__device__ __forceinline__ unsigned long long pack2(float lo, float hi) {
    unsigned long long r;
    asm("mov.b64 %0, {%1, %2};" : "=l"(r) : "f"(lo), "f"(hi));
    return r;
}
__device__ __forceinline__ void fma2(unsigned long long& acc,
                                     unsigned long long a,
                                     unsigned long long b) {
    asm("fma.rn.f32x2 %0, %1, %2, %0;" : "+l"(acc) : "l"(a), "l"(b));
}
__device__ __forceinline__ float2 unpack2(unsigned long long v) {
    float2 f;
    asm("mov.b64 {%0, %1}, %2;" : "=f"(f.x), "=f"(f.y) : "l"(v));
    return f;
}

// ---------- prep: m0 = mask(prelu(x)) ----------
__global__ void prep_kernel(const float4* __restrict__ x,
                            const float* __restrict__ pa,
                            float4* __restrict__ out, int n4) {
    int i = blockIdx.x * blockDim.x + threadIdx.x;
    if (i >= n4) return;
    float a = pa[0];
    float4 v = x[i];
    float4 r;
    {
        float t = v.x >= 0.f ? v.x : a * v.x;
        r.x = fabsf(t) >= 0.1f ? t : 0.f;
    }
    {
        float t = v.y >= 0.f ? v.y : a * v.y;
        r.y = fabsf(t) >= 0.1f ? t : 0.f;
    }
    {
        float t = v.z >= 0.f ? v.z : a * v.z;
        r.z = fabsf(t) >= 0.1f ? t : 0.f;
    }
    {
        float t = v.w >= 0.f ? v.w : a * v.w;
        r.w = fabsf(t) >= 0.1f ? t : 0.f;
    }
    out[i] = r;
}

// ---------- fused 3x3 conv ----------
// Block: 256 threads. Tile: 16x16 spatial x 64 output channels.
// Thread: 8 contiguous pixels (one row) x 8 output channels = 64 outputs,
// held as 32 f32x2 accumulators. C_in staged in chunks of 8 through smem.
//
// MODE 1: y=conv+b; xm=max(aux,y); outB=xm; outA=mask(prelu(xm))
// MODE 2: y=conv+b; xm=max(aux,y); outA=mask(prelu(xm))
// MODE 3: outA = y = conv+b
template <int MODE>
__global__ __launch_bounds__(256, 2)
void conv3x3_kernel(const float* __restrict__ in,
                    const float* __restrict__ w,
                    const float* __restrict__ bias,
                    const float* __restrict__ aux,
                    const float* __restrict__ pa,
                    float* __restrict__ outA,
                    float* __restrict__ outB) {
    __shared__ __align__(16) float xs[8][18][20];  // halo tile, padded rows
    __shared__ __align__(16) float ws[8][9][64];   // [ci][tap][oc]

    const int tid = threadIdx.x;
    const int tX  = (blockIdx.x & 7) * 16;
    const int tY  = (blockIdx.x >> 3) * 16;
    const int b   = blockIdx.y;
    const int ocb = blockIdx.z * 64;

    const int pix = tid & 31;
    const int og  = tid >> 5;     // 0..7: oc sub-group
    const int r   = pix & 15;     // row within tile
    const int cg  = pix >> 4;     // 0..1: column group
    const int c0  = cg * 8;

    unsigned long long acc[8][4];
#pragma unroll
    for (int o = 0; o < 8; o++)
#pragma unroll
        for (int j = 0; j < 4; j++) acc[o][j] = 0ull;

    for (int cbase = 0; cbase < C_; cbase += 8) {
        // ---- stage input halo (8 ci x 18 x 18, zero-padded at borders) ----
        for (int i = tid; i < 8 * 18 * 18; i += 256) {
            int ci  = i / 324;
            int rem = i - ci * 324;
            int rr  = rem / 18;
            int cc  = rem - rr * 18;
            int gy  = tY - 1 + rr;
            int gx  = tX - 1 + cc;
            float v = 0.f;
            if ((unsigned)gy < (unsigned)H_ && (unsigned)gx < (unsigned)W_)
                v = in[((b * C_ + cbase + ci) * H_ + gy) * W_ + gx];
            xs[ci][rr][cc] = v;
        }
        // ---- stage weights (contiguous global reads over (ci,tap)) ----
        for (int i = tid; i < 8 * 576; i += 256) {
            int oc  = i / 72;           // 0..63
            int rr  = i - oc * 72;      // 0..71 = ci*9+tap
            int ci  = rr / 9;
            int tap = rr - ci * 9;
            ws[ci][tap][oc] = w[(ocb + oc) * (C_ * 9) + cbase * 9 + rr];
        }
        __syncthreads();

#pragma unroll
        for (int ci = 0; ci < 8; ci++) {
#pragma unroll
            for (int ky = 0; ky < 3; ky++) {
                const float* row = &xs[ci][r + ky][c0];
                float4 A  = *(const float4*)(row);
                float4 Bv = *(const float4*)(row + 4);
                float2 Cv = *(const float2*)(row + 8);
                float v0 = A.x,  v1 = A.y,  v2 = A.z,  v3 = A.w;
                float v4 = Bv.x, v5 = Bv.y, v6 = Bv.z, v7 = Bv.w;
                float v8 = Cv.x, v9 = Cv.y;
                float vv[10] = {v0, v1, v2, v3, v4, v5, v6, v7, v8, v9};
#pragma unroll
                for (int kx = 0; kx < 3; kx++) {
                    unsigned long long p0 = pack2(vv[kx + 0], vv[kx + 1]);
                    unsigned long long p1 = pack2(vv[kx + 2], vv[kx + 3]);
                    unsigned long long p2 = pack2(vv[kx + 4], vv[kx + 5]);
                    unsigned long long p3 = pack2(vv[kx + 6], vv[kx + 7]);
                    const float* wrow = &ws[ci][ky * 3 + kx][og * 8];
#pragma unroll
                    for (int o = 0; o < 8; o++) {
                        float wv = wrow[o];
                        unsigned long long wp = pack2(wv, wv);
                        fma2(acc[o][0], p0, wp);
                        fma2(acc[o][1], p1, wp);
                        fma2(acc[o][2], p2, wp);
                        fma2(acc[o][3], p3, wp);
                    }
                }
            }
        }
        __syncthreads();
    }

    // ---- fused epilogue ----
    const float pav = pa[0];
    const int gy  = tY + r;
    const int gx0 = tX + c0;
#pragma unroll
    for (int o = 0; o < 8; o++) {
        const int oc = ocb + og * 8 + o;
        const float bv = bias[oc];
        const int base = ((b * C_ + oc) * H_ + gy) * W_ + gx0;
#pragma unroll
        for (int j = 0; j < 4; j++) {
            float2 v = unpack2(acc[o][j]);
            float y0 = v.x + bv;
            float y1 = v.y + bv;
            int idx = base + 2 * j;
            if (MODE == 1 || MODE == 2) {
                float m0 = fmaxf(aux[idx], y0);
                float m1 = fmaxf(aux[idx + 1], y1);
                if (MODE == 1) {
                    outB[idx]     = m0;
                    outB[idx + 1] = m1;
                }
                float t0 = m0 >= 0.f ? m0 : pav * m0;
                float t1 = m1 >= 0.f ? m1 : pav * m1;
                outA[idx]     = fabsf(t0) >= 0.1f ? t0 : 0.f;
                outA[idx + 1] = fabsf(t1) >= 0.1f ? t1 : 0.f;
            } else {
                outA[idx]     = y0;
                outA[idx + 1] = y1;
            }
        }
    }
}

extern "C" void kernel_launch(void* const* d_in, const int* in_sizes, int n_in,
                              void* d_out, int out_size) {
    const float* x  = (const float*)d_in[0];
    const float* w1 = (const float*)d_in[1];
    const float* b1 = (const float*)d_in[2];
    const float* w2 = (const float*)d_in[3];
    const float* b2 = (const float*)d_in[4];
    const float* w3 = (const float*)d_in[5];
    const float* b3 = (const float*)d_in[6];
    const float* pa = (const float*)d_in[7];
    float* out = (float*)d_out;

    float *p0, *p1, *p2;
    cudaGetSymbolAddress((void**)&p0, g_b0);
    cudaGetSymbolAddress((void**)&p1, g_b1);
    cudaGetSymbolAddress((void**)&p2, g_b2);

    const int n4 = N_ELEM / 4;
    prep_kernel<<<(n4 + 255) / 256, 256>>>((const float4*)x, pa, (float4*)p0, n4);

    dim3 grid(64, B_, 4);
    // conv1: in=m0, aux=x           -> outA=m1 (b1buf), outB=x1_max
    conv3x3_kernel<1><<<grid, 256>>>(p0, w1, b1, x,  pa, p1, p2);
    // conv2: in=m1, aux=x1_max      -> outA=m2 (reuse b0)
    conv3x3_kernel<2><<<grid, 256>>>(p1, w2, b2, p2, pa, p0, nullptr);
    // conv3: in=m2                  -> out
    conv3x3_kernel<3><<<grid, 256>>>(p0, w3, b3, nullptr, pa, out, nullptr);
}

// round 4
// speedup vs baseline: 1.0564x; 1.0564x over previous
#include <cuda_runtime.h>

// Problem constants
#define B_  8
#define C_  256
#define H_  128
#define W_  128
#define N_ELEM (B_*C_*H_*W_)   // 33,554,432 floats = 134.2 MB

// Scratch buffers (no cudaMalloc allowed)
__device__ float g_b0[N_ELEM];
__device__ float g_b1[N_ELEM];
__device__ float g_b2[N_ELEM];

// ---------- packed f32x2 helpers (sm_103a FFMA2 path) ----------
__device__ __forceinline__ unsigned long long pack2(float lo, float hi) {
    unsigned long long r;
    asm("mov.b64 %0, {%1, %2};" : "=l"(r) : "f"(lo), "f"(hi));
    return r;
}
__device__ __forceinline__ void fma2(unsigned long long& acc,
                                     unsigned long long a,
                                     unsigned long long b) {
    asm("fma.rn.f32x2 %0, %1, %2, %0;" : "+l"(acc) : "l"(a), "l"(b));
}
__device__ __forceinline__ float2 unpack2(unsigned long long v) {
    float2 f;
    asm("mov.b64 {%0, %1}, %2;" : "=f"(f.x), "=f"(f.y) : "l"(v));
    return f;
}

// ---------- prep: m0 = mask(prelu(x)) ----------
__global__ void prep_kernel(const float4* __restrict__ x,
                            const float* __restrict__ pa,
                            float4* __restrict__ out, int n4) {
    int i = blockIdx.x * blockDim.x + threadIdx.x;
    if (i >= n4) return;
    float a = pa[0];
    float4 v = x[i];
    float4 r;
    {
        float t = v.x >= 0.f ? v.x : a * v.x;
        r.x = fabsf(t) >= 0.1f ? t : 0.f;
    }
    {
        float t = v.y >= 0.f ? v.y : a * v.y;
        r.y = fabsf(t) >= 0.1f ? t : 0.f;
    }
    {
        float t = v.z >= 0.f ? v.z : a * v.z;
        r.z = fabsf(t) >= 0.1f ? t : 0.f;
    }
    {
        float t = v.w >= 0.f ? v.w : a * v.w;
        r.w = fabsf(t) >= 0.1f ? t : 0.f;
    }
    out[i] = r;
}

// ---------- fused 3x3 conv ----------
// Block: 256 threads. Tile: 16x16 spatial x 64 output channels.
// Thread: 8 contiguous pixels (one row) x 8 output channels = 64 outputs,
// held as 32 f32x2 accumulators. C_in staged in chunks of 8 through smem.
//
// MODE 1: y=conv+b; xm=max(aux,y); outB=xm; outA=mask(prelu(xm))
// MODE 2: y=conv+b; xm=max(aux,y); outA=mask(prelu(xm))
// MODE 3: outA = y = conv+b
template <int MODE>
__global__ __launch_bounds__(256, 2)
void conv3x3_kernel(const float* __restrict__ in,
                    const float* __restrict__ w,
                    const float* __restrict__ bias,
                    const float* __restrict__ aux,
                    const float* __restrict__ pa,
                    float* __restrict__ outA,
                    float* __restrict__ outB) {
    __shared__ __align__(16) float xs[8][18][20];  // halo tile, padded rows
    __shared__ __align__(16) float ws[8][9][64];   // [ci][tap][oc]

    const int tid = threadIdx.x;
    const int tX  = (blockIdx.x & 7) * 16;
    const int tY  = (blockIdx.x >> 3) * 16;
    const int b   = blockIdx.y;
    const int ocb = blockIdx.z * 64;

    const int pix = tid & 31;
    const int og  = tid >> 5;     // 0..7: oc sub-group
    const int r   = pix & 15;     // row within tile
    const int cg  = pix >> 4;     // 0..1: column group
    const int c0  = cg * 8;

    unsigned long long acc[8][4];
#pragma unroll
    for (int o = 0; o < 8; o++)
#pragma unroll
        for (int j = 0; j < 4; j++) acc[o][j] = 0ull;

    for (int cbase = 0; cbase < C_; cbase += 8) {
        // ---- stage input halo (8 ci x 18 x 18, zero-padded at borders) ----
        for (int i = tid; i < 8 * 18 * 18; i += 256) {
            int ci  = i / 324;
            int rem = i - ci * 324;
            int rr  = rem / 18;
            int cc  = rem - rr * 18;
            int gy  = tY - 1 + rr;
            int gx  = tX - 1 + cc;
            float v = 0.f;
            if ((unsigned)gy < (unsigned)H_ && (unsigned)gx < (unsigned)W_)
                v = in[((b * C_ + cbase + ci) * H_ + gy) * W_ + gx];
            xs[ci][rr][cc] = v;
        }
        // ---- stage weights (contiguous global reads over (ci,tap)) ----
        for (int i = tid; i < 8 * 576; i += 256) {
            int oc  = i / 72;           // 0..63
            int rr  = i - oc * 72;      // 0..71 = ci*9+tap
            int ci  = rr / 9;
            int tap = rr - ci * 9;
            ws[ci][tap][oc] = w[(ocb + oc) * (C_ * 9) + cbase * 9 + rr];
        }
        __syncthreads();

#pragma unroll
        for (int ci = 0; ci < 8; ci++) {
#pragma unroll
            for (int ky = 0; ky < 3; ky++) {
                const float* row = &xs[ci][r + ky][c0];
                float4 A  = *(const float4*)(row);
                float4 Bv = *(const float4*)(row + 4);
                float2 Cv = *(const float2*)(row + 8);
                float v0 = A.x,  v1 = A.y,  v2 = A.z,  v3 = A.w;
                float v4 = Bv.x, v5 = Bv.y, v6 = Bv.z, v7 = Bv.w;
                float v8 = Cv.x, v9 = Cv.y;
                float vv[10] = {v0, v1, v2, v3, v4, v5, v6, v7, v8, v9};
#pragma unroll
                for (int kx = 0; kx < 3; kx++) {
                    unsigned long long p0 = pack2(vv[kx + 0], vv[kx + 1]);
                    unsigned long long p1 = pack2(vv[kx + 2], vv[kx + 3]);
                    unsigned long long p2 = pack2(vv[kx + 4], vv[kx + 5]);
                    unsigned long long p3 = pack2(vv[kx + 6], vv[kx + 7]);
                    const float* wrow = &ws[ci][ky * 3 + kx][og * 8];
#pragma unroll
                    for (int o = 0; o < 8; o++) {
                        float wv = wrow[o];
                        unsigned long long wp = pack2(wv, wv);
                        fma2(acc[o][0], p0, wp);
                        fma2(acc[o][1], p1, wp);
                        fma2(acc[o][2], p2, wp);
                        fma2(acc[o][3], p3, wp);
                    }
                }
            }
        }
        __syncthreads();
    }

    // ---- fused epilogue ----
    const float pav = pa[0];
    const int gy  = tY + r;
    const int gx0 = tX + c0;
#pragma unroll
    for (int o = 0; o < 8; o++) {
        const int oc = ocb + og * 8 + o;
        const float bv = bias[oc];
        const int base = ((b * C_ + oc) * H_ + gy) * W_ + gx0;
#pragma unroll
        for (int j = 0; j < 4; j++) {
            float2 v = unpack2(acc[o][j]);
            float y0 = v.x + bv;
            float y1 = v.y + bv;
            int idx = base + 2 * j;
            if (MODE == 1 || MODE == 2) {
                float m0 = fmaxf(aux[idx], y0);
                float m1 = fmaxf(aux[idx + 1], y1);
                if (MODE == 1) {
                    outB[idx]     = m0;
                    outB[idx + 1] = m1;
                }
                float t0 = m0 >= 0.f ? m0 : pav * m0;
                float t1 = m1 >= 0.f ? m1 : pav * m1;
                outA[idx]     = fabsf(t0) >= 0.1f ? t0 : 0.f;
                outA[idx + 1] = fabsf(t1) >= 0.1f ? t1 : 0.f;
            } else {
                outA[idx]     = y0;
                outA[idx + 1] = y1;
            }
        }
    }
}

extern "C" void kernel_launch(void* const* d_in, const int* in_sizes, int n_in,
                              void* d_out, int out_size) {
    const float* x  = (const float*)d_in[0];
    const float* w1 = (const float*)d_in[1];
    const float* b1 = (const float*)d_in[2];
    const float* w2 = (const float*)d_in[3];
    const float* b2 = (const float*)d_in[4];
    const float* w3 = (const float*)d_in[5];
    const float* b3 = (const float*)d_in[6];
    const float* pa = (const float*)d_in[7];
    float* out = (float*)d_out;

    float *p0, *p1, *p2;
    cudaGetSymbolAddress((void**)&p0, g_b0);
    cudaGetSymbolAddress((void**)&p1, g_b1);
    cudaGetSymbolAddress((void**)&p2, g_b2);

    const int n4 = N_ELEM / 4;
    prep_kernel<<<(n4 + 255) / 256, 256>>>((const float4*)x, pa, (float4*)p0, n4);

    dim3 grid(64, B_, 4);
    // conv1: in=m0, aux=x           -> outA=m1 (b1buf), outB=x1_max
    conv3x3_kernel<1><<<grid, 256>>>(p0, w1, b1, x,  pa, p1, p2);
    // conv2: in=m1, aux=x1_max      -> outA=m2 (reuse b0)
    conv3x3_kernel<2><<<grid, 256>>>(p1, w2, b2, p2, pa, p0, nullptr);
    // conv3: in=m2                  -> out
    conv3x3_kernel<3><<<grid, 256>>>(p0, w3, b3, nullptr, pa, out, nullptr);
}

// round 7
// speedup vs baseline: 3.2826x; 3.1073x over previous
#include <cuda_runtime.h>
#include <cuda_bf16.h>
#include <cstdint>

#define Bn 8
#define Cn 256
#define Hn 128
#define Wn 128
#define NE (Bn*Cn*Hn*Wn)

#define ROWB   192                 // gmem act row: 96 bf16 (hi32|hi32|lo32)
#define SROWB  256                 // smem A pitch
#define ABLK   (130*ROWB)          // 24960 B per (b,y,g) block (rows 0,129 = zero halo)
#define ACT_TOT ((size_t)Bn*Hn*8*ABLK)
#define WSTG   73728               // W bytes per (ocH,ky,g) stage
#define WCONV  (48ull*WSTG)        // 3,538,944 B per conv
#define ASTG   33280               // 130*256
#define STG    (ASTG + WSTG)       // 107008
#define DSMEM  (2*STG)             // 214016

__device__ __align__(1024) unsigned char g_actA[ACT_TOT];
__device__ __align__(1024) unsigned char g_actB[ACT_TOT];
__device__ __align__(1024) unsigned char g_wpk[3*WCONV];
__device__ __align__(1024) unsigned char g_zero[ABLK];
__device__ float g_xm[NE];

// ---------------- helpers ----------------
static __device__ __forceinline__ uint32_t smem_u32(const void* p) {
    uint32_t r;
    asm("{ .reg .u64 t; cvta.to.shared.u64 t, %1; cvt.u32.u64 %0, t; }" : "=r"(r) : "l"(p));
    return r;
}
static __device__ __forceinline__ void cp16(uint32_t dst, const void* src) {
    asm volatile("cp.async.cg.shared.global [%0], [%1], 16;" :: "r"(dst), "l"(src) : "memory");
}
#define CP_COMMIT() asm volatile("cp.async.commit_group;" ::: "memory")
#define CP_WAIT1()  asm volatile("cp.async.wait_group 1;" ::: "memory")
#define CP_WAIT0()  asm volatile("cp.async.wait_group 0;" ::: "memory")

static __device__ __forceinline__ void ldm4(uint32_t a[4], uint32_t addr) {
    asm volatile("ldmatrix.sync.aligned.m8n8.x4.shared.b16 {%0,%1,%2,%3}, [%4];"
                 : "=r"(a[0]), "=r"(a[1]), "=r"(a[2]), "=r"(a[3]) : "r"(addr));
}
static __device__ __forceinline__ void mma16816(float d[4], const uint32_t a[4],
                                                uint32_t b0, uint32_t b1) {
    asm volatile("mma.sync.aligned.m16n8k16.row.col.f32.bf16.bf16.f32 "
                 "{%0,%1,%2,%3}, {%4,%5,%6,%7}, {%8,%9}, {%0,%1,%2,%3};"
                 : "+f"(d[0]), "+f"(d[1]), "+f"(d[2]), "+f"(d[3])
                 : "r"(a[0]), "r"(a[1]), "r"(a[2]), "r"(a[3]), "r"(b0), "r"(b1));
}
static __device__ __forceinline__ void split_bf16(float a, unsigned short& hb, unsigned short& lb) {
    __nv_bfloat16 h = __float2bfloat16(a);
    float hf = __bfloat162float(h);
    __nv_bfloat16 l = __float2bfloat16(a - hf);
    hb = __bfloat16_as_ushort(h);
    lb = __bfloat16_as_ushort(l);
}
// build packed row regs from 32 fp32 values (j-pairs), then store 192B (hi,hi,lo)
static __device__ __forceinline__ void store_row(unsigned char* dst,
                                                 const uint32_t hv[16], const uint32_t lv[16]) {
    uint4* d4 = (uint4*)dst;
#pragma unroll
    for (int i = 0; i < 4; i++) {
        uint4 h = make_uint4(hv[4*i], hv[4*i+1], hv[4*i+2], hv[4*i+3]);
        d4[i] = h;          // k 0..31  : hi
        d4[i + 4] = h;      // k 32..63 : hi (pairs with loW)
        d4[i + 8] = make_uint4(lv[4*i], lv[4*i+1], lv[4*i+2], lv[4*i+3]); // k 64..95 : lo
    }
}

// ---------------- init: zero block + act halo rows ----------------
__global__ void k_zero() {
    int i = blockIdx.x * blockDim.x + threadIdx.x;
    const uint4 z = make_uint4(0, 0, 0, 0);
    if (i < 1560) { ((uint4*)g_zero)[i] = z; return; }
    int h = i - 1560;
    if (h >= 2 * Bn * Hn * 8 * 2 * 12) return;   // 2 bufs, 8192 blocks, 2 rows, 12 chunks
    int c = h % 12;  h /= 12;
    int rsel = h & 1; h >>= 1;
    int blk = h & 8191; h >>= 13;
    unsigned char* buf = h ? g_actB : g_actA;
    *(uint4*)(buf + (size_t)blk * ABLK + (rsel ? 129 : 0) * ROWB + c * 16) = z;
}

// ---------------- weight pack: per-lane mma B-fragment order ----------------
// layout u32: [ocH2][ky3][g8][kx3][ks6][nt16][lane32][j2]
__global__ void k_packw(const float* __restrict__ w, unsigned char* __restrict__ dstB) {
    int u = blockIdx.x * blockDim.x + threadIdx.x;
    if (u >= 884736) return;
    int j    = u & 1;        int r = u >> 1;
    int lane = r & 31;       r >>= 5;
    int nt   = r & 15;       r >>= 4;
    int ks   = r % 6;        r /= 6;
    int kx   = r % 3;        r /= 3;
    int g    = r & 7;        r >>= 3;
    int ky   = r % 3;        r /= 3;
    int ocH  = r;            // 0..1
    int oc = ocH * 128 + nt * 8 + (lane >> 2);
    int k  = ks * 16 + (lane & 3) * 2 + j * 8;     // even, k and k+1 same term
    int term = k >> 5;                              // 0:hi 1:lo 2:hi
    int ci0 = g * 32 + (k & 31);
    float e0 = w[((oc * Cn + ci0) * 3 + ky) * 3 + kx];
    float e1 = w[((oc * Cn + ci0 + 1) * 3 + ky) * 3 + kx];
    unsigned short h0, l0, h1, l1;
    split_bf16(e0, h0, l0);
    split_bf16(e1, h1, l1);
    unsigned short v0 = (term == 1) ? l0 : h0;
    unsigned short v1 = (term == 1) ? l1 : h1;
    ((uint32_t*)dstB)[u] = (uint32_t)v0 | ((uint32_t)v1 << 16);
}

// ---------------- prep: act0 = split(mask(prelu(x))) ----------------
__global__ void k_prep(const float* __restrict__ x, const float* __restrict__ pa) {
    extern __shared__ float sX[];   // [ci 256][px 128]
    const int y = blockIdx.x, b = blockIdx.y, tid = threadIdx.x;
    const float pav = pa[0];
    const float4* src = (const float4*)(x + ((size_t)b * Cn * Hn + y) * Wn);
    // x[b][ci][y][px]: row (ci) stride = Hn*Wn/4 float4
    for (int i = tid; i < 8192; i += 256) {
        int ci = i >> 5, p4 = i & 31;
        ((float4*)sX)[ci * 32 + p4] = src[(size_t)ci * (Hn * Wn / 4) + p4];
    }
    __syncthreads();
#pragma unroll 1
    for (int k = 0; k < 4; k++) {
        int t = tid + k * 256;
        int px = t & 127, g = t >> 7;
        uint32_t hv[16], lv[16];
        unsigned short hprev = 0, lprev = 0;
#pragma unroll
        for (int j = 0; j < 32; j++) {
            float v = sX[(g * 32 + j) * 128 + px];
            float tt = v >= 0.f ? v : pav * v;
            float a = fabsf(tt) >= 0.1f ? tt : 0.f;
            unsigned short hb, lb;
            split_bf16(a, hb, lb);
            if (j & 1) { hv[j >> 1] = (uint32_t)hprev | ((uint32_t)hb << 16);
                         lv[j >> 1] = (uint32_t)lprev | ((uint32_t)lb << 16); }
            else { hprev = hb; lprev = lb; }
        }
        store_row(g_actA + ((size_t)(b * Hn + y) * 8 + g) * ABLK + (px + 1) * ROWB, hv, lv);
    }
}

// ---------------- main conv: mma.sync implicit GEMM ----------------
// MODE 1: y=conv+bias; m=max(xm,y); xm=m; actOut=pack(mask(prelu(m)))
// MODE 3: out(NCHW fp32) = conv+bias
template <int MODE>
__global__ __launch_bounds__(256)
void conv_mma(const unsigned char* __restrict__ actIn,
              const unsigned char* __restrict__ wcv,
              const float* __restrict__ bias,
              float* __restrict__ xm,
              const float* __restrict__ pa,
              unsigned char* __restrict__ actOut,
              float* __restrict__ out) {
    extern __shared__ __align__(16) unsigned char dsm[];
    const uint32_t sb = smem_u32(dsm);
    const int tid = threadIdx.x, lane = tid & 31, wid = tid >> 5;
    const int ocH = blockIdx.x, y = blockIdx.y, b = blockIdx.z;
    const int mW = (wid & 3) * 32;          // warp M origin (px)
    const int ntB = (wid >> 2) * 8;         // warp n8-tile base (n = nt*8)

    float d[2][8][4];
#pragma unroll
    for (int mt = 0; mt < 2; mt++)
#pragma unroll
        for (int nt = 0; nt < 8; nt++)
#pragma unroll
            for (int q = 0; q < 4; q++) d[mt][nt][q] = 0.f;

    // stage issue: (ky,g) = (it/8, it%8)
    #define ISSUE(IT) do { \
        int s_ = (IT) & 1; \
        int ky_ = (IT) >> 3, g_ = (IT) & 7; \
        int ys_ = y + ky_ - 1; \
        const unsigned char* aSrc = ((unsigned)ys_ < (unsigned)Hn) \
            ? actIn + ((size_t)(b * Hn + ys_) * 8 + g_) * ABLK : g_zero; \
        const unsigned char* wSrc = wcv + (size_t)((ocH * 3 + ky_) * 8 + g_) * WSTG; \
        uint32_t ab = sb + s_ * STG; \
        for (int i = tid; i < 1560; i += 256) { \
            int row = i / 12, c = i - row * 12; \
            cp16(ab + row * SROWB + ((c ^ (row & 7)) << 4), aSrc + row * ROWB + c * 16); \
        } \
        uint32_t wb = ab + ASTG; \
        for (int i = tid; i < 4608; i += 256) \
            cp16(wb + i * 16, wSrc + (size_t)i * 16); \
        CP_COMMIT(); \
    } while (0)

    ISSUE(0);
    ISSUE(1);

    for (int it = 0; it < 24; it++) {
        const int s = it & 1;
        CP_WAIT1();
        __syncthreads();
        const uint32_t aB = sb + s * STG;
        const unsigned char* wS = dsm + s * STG + ASTG;
#pragma unroll 1
        for (int ks = 0; ks < 6; ks++) {
#pragma unroll
            for (int kx = 0; kx < 3; kx++) {
                uint32_t aF[2][4];
#pragma unroll
                for (int mt = 0; mt < 2; mt++) {
                    int row = mW + mt * 16 + (lane & 15) + kx;   // 0..129
                    int c = ks * 2 + (lane >> 4);
                    ldm4(aF[mt], aB + row * SROWB + ((c ^ (row & 7)) << 4));
                }
                const uint2* wrow = (const uint2*)(wS + ((size_t)(kx * 6 + ks) * 16 + ntB) * 256);
#pragma unroll
                for (int nt = 0; nt < 8; nt++) {
                    uint2 bf = wrow[nt * 32 + lane];
                    mma16816(d[0][nt], aF[0], bf.x, bf.y);
                    mma16816(d[1][nt], aF[1], bf.x, bf.y);
                }
            }
        }
        __syncthreads();
        if (it + 2 < 24) ISSUE(it + 2);
    }
    #undef ISSUE
    CP_WAIT0();
    __syncthreads();

    // ---- epilogue: fragments -> smem fp32 tile [px][oc] pitch 129 ----
    float* sD = (float*)dsm;
#pragma unroll
    for (int mt = 0; mt < 2; mt++) {
        int m0 = mW + mt * 16 + (lane >> 2);
        int n0base = ntB * 8 + (lane & 3) * 2;
#pragma unroll
        for (int nt = 0; nt < 8; nt++) {
            int n0 = n0base + nt * 8;
            sD[m0 * 129 + n0]           = d[mt][nt][0];
            sD[m0 * 129 + n0 + 1]       = d[mt][nt][1];
            sD[(m0 + 8) * 129 + n0]     = d[mt][nt][2];
            sD[(m0 + 8) * 129 + n0 + 1] = d[mt][nt][3];
        }
    }
    __syncthreads();

    const float pav = pa[0];
#pragma unroll 1
    for (int k = 0; k < 2; k++) {
        int t = tid + k * 256;
        int px = t & 127, gl = t >> 7;               // gl 0..3
        int oc0 = ocH * 128 + gl * 32;
        if (MODE == 1) {
            uint32_t hv[16], lv[16];
            unsigned short hprev = 0, lprev = 0;
#pragma unroll
            for (int j = 0; j < 32; j++) {
                float v = sD[px * 129 + gl * 32 + j] + bias[oc0 + j];
                size_t xi = ((size_t)(b * Cn + oc0 + j) * Hn + y) * Wn + px;
                float m = fmaxf(xm[xi], v);
                xm[xi] = m;
                float tt = m >= 0.f ? m : pav * m;
                float a = fabsf(tt) >= 0.1f ? tt : 0.f;
                unsigned short hb, lb;
                split_bf16(a, hb, lb);
                if (j & 1) { hv[j >> 1] = (uint32_t)hprev | ((uint32_t)hb << 16);
                             lv[j >> 1] = (uint32_t)lprev | ((uint32_t)lb << 16); }
                else { hprev = hb; lprev = lb; }
            }
            int gOut = ocH * 4 + gl;
            store_row(actOut + ((size_t)(b * Hn + y) * 8 + gOut) * ABLK + (px + 1) * ROWB, hv, lv);
        } else {
#pragma unroll
            for (int j = 0; j < 32; j++) {
                float v = sD[px * 129 + gl * 32 + j] + bias[oc0 + j];
                out[((size_t)(b * Cn + oc0 + j) * Hn + y) * Wn + px] = v;
            }
        }
    }
}

// ---------------- host ----------------
extern "C" void kernel_launch(void* const* d_in, const int* in_sizes, int n_in,
                              void* d_out, int out_size) {
    const float* x  = (const float*)d_in[0];
    const float* w1 = (const float*)d_in[1];
    const float* b1 = (const float*)d_in[2];
    const float* w2 = (const float*)d_in[3];
    const float* b2 = (const float*)d_in[4];
    const float* w3 = (const float*)d_in[5];
    const float* b3 = (const float*)d_in[6];
    const float* pa = (const float*)d_in[7];
    float* out = (float*)d_out;

    unsigned char *wpk;
    float* xm;
    cudaGetSymbolAddress((void**)&wpk, g_wpk);
    cudaGetSymbolAddress((void**)&xm,  g_xm);
    unsigned char *actA, *actB;
    cudaGetSymbolAddress((void**)&actA, g_actA);
    cudaGetSymbolAddress((void**)&actB, g_actB);

    static int attr_done = 0;
    cudaFuncSetAttribute(conv_mma<1>, cudaFuncAttributeMaxDynamicSharedMemorySize, DSMEM);
    cudaFuncSetAttribute(conv_mma<3>, cudaFuncAttributeMaxDynamicSharedMemorySize, DSMEM);
    cudaFuncSetAttribute(k_prep, cudaFuncAttributeMaxDynamicSharedMemorySize, 131072);
    (void)attr_done;

    k_zero<<<(1560 + 786432 + 255) / 256, 256>>>();
    k_packw<<<3456, 256>>>(w1, wpk);
    k_packw<<<3456, 256>>>(w2, wpk + WCONV);
    k_packw<<<3456, 256>>>(w3, wpk + 2 * WCONV);
    cudaMemcpyAsync(xm, x, (size_t)NE * 4, cudaMemcpyDeviceToDevice);
    k_prep<<<dim3(Hn, Bn), 256, 131072>>>(x, pa);

    dim3 grid(2, Hn, Bn);
    conv_mma<1><<<grid, 256, DSMEM>>>(actA, wpk,             b1, xm, pa, actB, nullptr);
    conv_mma<1><<<grid, 256, DSMEM>>>(actB, wpk + WCONV,     b2, xm, pa, actA, nullptr);
    conv_mma<3><<<grid, 256, DSMEM>>>(actA, wpk + 2 * WCONV, b3, xm, pa, nullptr, out);
}

// round 8
// speedup vs baseline: 5.1474x; 1.5681x over previous
#include <cuda_runtime.h>
#include <cuda_fp16.h>
#include <cstdint>

#define Bn 8
#define Cn 256
#define Hn 128
#define Wn 128
#define NE (Bn*Cn*Hn*Wn)

#define ROWB   128                  // gmem act row: 64 fp16 (hi32 | lo32)
#define ABLK   (130*ROWB)           // 16640 B per (b,y,g) block (rows 0,129 zero halo)
#define ACT_TOT ((size_t)Bn*Hn*8*ABLK)
#define WSTG   49152                // W bytes per (ocH,ky,g) stage: 3kx*4ks*16nt*32ln*8B
#define WCONV  (48ull*WSTG)
#define ASTG   (2*ABLK)             // 33280: two input-row blocks
#define STG    (ASTG + WSTG)        // 82432
#define DSMEM  (2*STG)              // 164864
#define DSMEM_REQ (DSMEM + 1024)

__device__ __align__(1024) unsigned char g_actA[ACT_TOT];
__device__ __align__(1024) unsigned char g_actB[ACT_TOT];
__device__ __align__(1024) unsigned char g_wpk[3*WCONV];
__device__ __align__(1024) unsigned char g_zero[ABLK];
__device__ float g_xm[NE];

// ---------------- helpers ----------------
static __device__ __forceinline__ uint32_t smem_u32(const void* p) {
    uint32_t r;
    asm("{ .reg .u64 t; cvta.to.shared.u64 t, %1; cvt.u32.u64 %0, t; }" : "=r"(r) : "l"(p));
    return r;
}
static __device__ __forceinline__ void cp16(uint32_t dst, const void* src) {
    asm volatile("cp.async.cg.shared.global [%0], [%1], 16;" :: "r"(dst), "l"(src) : "memory");
}
#define CP_COMMIT() asm volatile("cp.async.commit_group;" ::: "memory")
#define CP_WAIT1()  asm volatile("cp.async.wait_group 1;" ::: "memory")
#define CP_WAIT0()  asm volatile("cp.async.wait_group 0;" ::: "memory")

static __device__ __forceinline__ void ldm4(uint32_t a[4], uint32_t addr) {
    asm volatile("ldmatrix.sync.aligned.m8n8.x4.shared.b16 {%0,%1,%2,%3}, [%4];"
                 : "=r"(a[0]), "=r"(a[1]), "=r"(a[2]), "=r"(a[3]) : "r"(addr));
}
static __device__ __forceinline__ void mma16816(float d[4], const uint32_t a[4],
                                                uint32_t b0, uint32_t b1) {
    asm volatile("mma.sync.aligned.m16n8k16.row.col.f32.f16.f16.f32 "
                 "{%0,%1,%2,%3}, {%4,%5,%6,%7}, {%8,%9}, {%0,%1,%2,%3};"
                 : "+f"(d[0]), "+f"(d[1]), "+f"(d[2]), "+f"(d[3])
                 : "r"(a[0]), "r"(a[1]), "r"(a[2]), "r"(a[3]), "r"(b0), "r"(b1));
}
static __device__ __forceinline__ void split_f16(float a, unsigned short& hb, unsigned short& lb) {
    __half h = __float2half_rn(a);
    float hf = __half2float(h);
    __half l = __float2half_rn(a - hf);
    hb = __half_as_ushort(h);
    lb = __half_as_ushort(l);
}
// store one act row: 128B = [hi 32ci | lo 32ci]
static __device__ __forceinline__ void store_row(unsigned char* dst,
                                                 const uint32_t hv[16], const uint32_t lv[16]) {
    uint4* d4 = (uint4*)dst;
#pragma unroll
    for (int i = 0; i < 4; i++) {
        d4[i]     = make_uint4(hv[4*i], hv[4*i+1], hv[4*i+2], hv[4*i+3]);
        d4[i + 4] = make_uint4(lv[4*i], lv[4*i+1], lv[4*i+2], lv[4*i+3]);
    }
}

// ---------------- init: zero block + act halo rows ----------------
__global__ void k_zero() {
    int i = blockIdx.x * blockDim.x + threadIdx.x;
    const uint4 z = make_uint4(0, 0, 0, 0);
    if (i < 1040) { ((uint4*)g_zero)[i] = z; return; }
    int h = i - 1040;
    if (h >= 2 * 8192 * 2 * 8) return;     // 2 bufs x 8192 blocks x 2 rows x 8 chunks
    int c = h & 7;   h >>= 3;
    int rsel = h & 1; h >>= 1;
    int blk = h & 8191; h >>= 13;
    unsigned char* buf = h ? g_actB : g_actA;
    *(uint4*)(buf + (size_t)blk * ABLK + (rsel ? 129 : 0) * ROWB + c * 16) = z;
}

// ---------------- weight pack ----------------
// u32 layout: [ocH2][ky3][g8][kx3][ks4][nt16][lane32][j2]; both k-halves = hW
__global__ void k_packw(const float* __restrict__ w, unsigned char* __restrict__ dstB) {
    int u = blockIdx.x * blockDim.x + threadIdx.x;
    if (u >= 589824) return;
    int j    = u & 1;        int r = u >> 1;
    int lane = r & 31;       r >>= 5;
    int nt   = r & 15;       r >>= 4;
    int ks   = r & 3;        r >>= 2;
    int kx   = r % 3;        r /= 3;
    int g    = r & 7;        r >>= 3;
    int ky   = r % 3;        r /= 3;
    int ocH  = r;
    int oc = ocH * 128 + nt * 8 + (lane >> 2);
    int k  = ks * 16 + (lane & 3) * 2 + j * 8;
    int ci0 = g * 32 + (k & 31);
    float e0 = w[((oc * Cn + ci0) * 3 + ky) * 3 + kx];
    float e1 = w[((oc * Cn + ci0 + 1) * 3 + ky) * 3 + kx];
    unsigned short h0 = __half_as_ushort(__float2half_rn(e0));
    unsigned short h1 = __half_as_ushort(__float2half_rn(e1));
    ((uint32_t*)dstB)[u] = (uint32_t)h0 | ((uint32_t)h1 << 16);
}

// ---------------- prep: act0 = split(mask(prelu(x))) ----------------
__global__ void k_prep(const float* __restrict__ x, const float* __restrict__ pa) {
    extern __shared__ float sX[];   // [ci 256][px 128]
    const int y = blockIdx.x, b = blockIdx.y, tid = threadIdx.x;
    const float pav = pa[0];
    const float4* src = (const float4*)(x + ((size_t)b * Cn * Hn + y) * Wn);
    for (int i = tid; i < 8192; i += 256) {
        int ci = i >> 5, p4 = i & 31;
        ((float4*)sX)[ci * 32 + p4] = src[(size_t)ci * (Hn * Wn / 4) + p4];
    }
    __syncthreads();
#pragma unroll 1
    for (int k = 0; k < 4; k++) {
        int t = tid + k * 256;
        int px = t & 127, g = t >> 7;
        uint32_t hv[16], lv[16];
        unsigned short hprev = 0, lprev = 0;
#pragma unroll
        for (int j = 0; j < 32; j++) {
            float v = sX[(g * 32 + j) * 128 + px];
            float tt = v >= 0.f ? v : pav * v;
            float a = fabsf(tt) >= 0.1f ? tt : 0.f;
            unsigned short hb, lb;
            split_f16(a, hb, lb);
            if (j & 1) { hv[j >> 1] = (uint32_t)hprev | ((uint32_t)hb << 16);
                         lv[j >> 1] = (uint32_t)lprev | ((uint32_t)lb << 16); }
            else { hprev = hb; lprev = lb; }
        }
        store_row(g_actA + ((size_t)(b * Hn + y) * 8 + g) * ABLK + (px + 1) * ROWB, hv, lv);
    }
}

// ---------------- main conv: mma.sync implicit GEMM, M=256 N=128 ----------------
// MODE 1: y=conv+bias; m=max(xm,y); xm=m; actOut=pack(mask(prelu(m)))
// MODE 3: out(NCHW fp32) = conv+bias
template <int MODE>
__global__ __launch_bounds__(256)
void conv_mma(const unsigned char* __restrict__ actIn,
              const unsigned char* __restrict__ wcv,
              const float* __restrict__ bias,
              float* __restrict__ xm,
              const float* __restrict__ pa,
              unsigned char* __restrict__ actOut,
              float* __restrict__ out) {
    extern __shared__ __align__(16) unsigned char dsm_raw[];
    const uint32_t sb0 = smem_u32(dsm_raw);
    const uint32_t sb = (sb0 + 1023u) & ~1023u;
    unsigned char* dsm = dsm_raw + (sb - sb0);
    const int tid = threadIdx.x, lane = tid & 31, wid = tid >> 5;
    const int ocH = blockIdx.x, y = blockIdx.y * 2, b = blockIdx.z;
    const int mw = wid & 3;                 // M-warp 0..3 (M base = mw*64)
    const int ablk = mw >> 1;               // input-row block (out y / y+1)
    const int pxb = (mw & 1) * 64;          // px base within block
    const int ntB = (wid >> 2) * 8;         // N half: 8 n8-tiles

    float d[4][8][4];
#pragma unroll
    for (int mt = 0; mt < 4; mt++)
#pragma unroll
        for (int nt = 0; nt < 8; nt++)
#pragma unroll
            for (int q = 0; q < 4; q++) d[mt][nt][q] = 0.f;

    #define ISSUE(IT) do { \
        int s_ = (IT) & 1; \
        int ky_ = (IT) >> 3, g_ = (IT) & 7; \
        int ys0_ = y + ky_ - 1; \
        const unsigned char* a0 = ((unsigned)ys0_ < (unsigned)Hn) \
            ? actIn + ((size_t)(b * Hn + ys0_) * 8 + g_) * ABLK : g_zero; \
        const unsigned char* a1 = ((unsigned)(ys0_ + 1) < (unsigned)Hn) \
            ? actIn + ((size_t)(b * Hn + ys0_ + 1) * 8 + g_) * ABLK : g_zero; \
        const unsigned char* wSrc = wcv + (size_t)((ocH * 3 + ky_) * 8 + g_) * WSTG; \
        uint32_t ab = sb + s_ * STG; \
        for (int i = tid; i < 2080; i += 256) { \
            int bk = i >= 1040; int ii = i - bk * 1040; \
            int row = ii >> 3, c = ii & 7; \
            cp16(ab + bk * ABLK + row * ROWB + ((c ^ (row & 7)) << 4), \
                 (bk ? a1 : a0) + row * ROWB + c * 16); \
        } \
        uint32_t wb = ab + ASTG; \
        for (int i = tid; i < 3072; i += 256) \
            cp16(wb + i * 16, wSrc + (size_t)i * 16); \
        CP_COMMIT(); \
    } while (0)

    ISSUE(0);
    ISSUE(1);

    for (int it = 0; it < 24; it++) {
        const int s = it & 1;
        CP_WAIT1();
        __syncthreads();
        const uint32_t aB = sb + s * STG + ablk * ABLK;
        const unsigned char* wS = dsm + s * STG + ASTG;
#pragma unroll 1
        for (int ks = 0; ks < 4; ks++) {
#pragma unroll
            for (int kx = 0; kx < 3; kx++) {
                uint32_t aF[4][4];
#pragma unroll
                for (int mt = 0; mt < 4; mt++) {
                    int row = pxb + mt * 16 + (lane & 15) + kx;     // 0..129
                    int c = ks * 2 + (lane >> 4);
                    ldm4(aF[mt], aB + row * ROWB + ((c ^ (row & 7)) << 4));
                }
                const uint2* wrow = (const uint2*)(wS + ((size_t)(kx * 4 + ks) * 16 + ntB) * 256);
#pragma unroll
                for (int nt = 0; nt < 8; nt++) {
                    uint2 bf = wrow[nt * 32 + lane];
                    mma16816(d[0][nt], aF[0], bf.x, bf.y);
                    mma16816(d[1][nt], aF[1], bf.x, bf.y);
                    mma16816(d[2][nt], aF[2], bf.x, bf.y);
                    mma16816(d[3][nt], aF[3], bf.x, bf.y);
                }
            }
        }
        __syncthreads();
        if (it + 2 < 24) ISSUE(it + 2);
    }
    #undef ISSUE
    CP_WAIT0();
    __syncthreads();

    // ---- epilogue: fragments -> smem fp32 tile [m 256][oc 128] pitch 129 ----
    float* sD = (float*)dsm;
#pragma unroll
    for (int mt = 0; mt < 4; mt++) {
        int m0 = mw * 64 + mt * 16 + (lane >> 2);
        int n0base = ntB * 8 + (lane & 3) * 2;
#pragma unroll
        for (int nt = 0; nt < 8; nt++) {
            int n0 = n0base + nt * 8;
            sD[m0 * 129 + n0]           = d[mt][nt][0];
            sD[m0 * 129 + n0 + 1]       = d[mt][nt][1];
            sD[(m0 + 8) * 129 + n0]     = d[mt][nt][2];
            sD[(m0 + 8) * 129 + n0 + 1] = d[mt][nt][3];
        }
    }
    __syncthreads();

    const float pav = pa[0];
#pragma unroll 1
    for (int k = 0; k < 4; k++) {
        int t = tid + k * 256;
        int r = t & 255, gl = t >> 8;                // r = m row, gl = oc group
        int px = r & 127, dy = r >> 7;
        int yout = y + dy;
        int oc0 = ocH * 128 + gl * 32;
        if (MODE == 1) {
            uint32_t hv[16], lv[16];
            unsigned short hprev = 0, lprev = 0;
#pragma unroll
            for (int j = 0; j < 32; j++) {
                float v = sD[r * 129 + gl * 32 + j] + bias[oc0 + j];
                size_t xi = ((size_t)(b * Cn + oc0 + j) * Hn + yout) * Wn + px;
                float m = fmaxf(xm[xi], v);
                xm[xi] = m;
                float tt = m >= 0.f ? m : pav * m;
                float a = fabsf(tt) >= 0.1f ? tt : 0.f;
                unsigned short hb, lb;
                split_f16(a, hb, lb);
                if (j & 1) { hv[j >> 1] = (uint32_t)hprev | ((uint32_t)hb << 16);
                             lv[j >> 1] = (uint32_t)lprev | ((uint32_t)lb << 16); }
                else { hprev = hb; lprev = lb; }
            }
            int gOut = ocH * 4 + gl;
            store_row(actOut + ((size_t)(b * Hn + yout) * 8 + gOut) * ABLK + (px + 1) * ROWB, hv, lv);
        } else {
#pragma unroll
            for (int j = 0; j < 32; j++) {
                float v = sD[r * 129 + gl * 32 + j] + bias[oc0 + j];
                out[((size_t)(b * Cn + oc0 + j) * Hn + yout) * Wn + px] = v;
            }
        }
    }
}

// ---------------- host ----------------
extern "C" void kernel_launch(void* const* d_in, const int* in_sizes, int n_in,
                              void* d_out, int out_size) {
    const float* x  = (const float*)d_in[0];
    const float* w1 = (const float*)d_in[1];
    const float* b1 = (const float*)d_in[2];
    const float* w2 = (const float*)d_in[3];
    const float* b2 = (const float*)d_in[4];
    const float* w3 = (const float*)d_in[5];
    const float* b3 = (const float*)d_in[6];
    const float* pa = (const float*)d_in[7];
    float* out = (float*)d_out;

    unsigned char *wpk, *actA, *actB;
    float* xm;
    cudaGetSymbolAddress((void**)&wpk,  g_wpk);
    cudaGetSymbolAddress((void**)&xm,   g_xm);
    cudaGetSymbolAddress((void**)&actA, g_actA);
    cudaGetSymbolAddress((void**)&actB, g_actB);

    cudaFuncSetAttribute(conv_mma<1>, cudaFuncAttributeMaxDynamicSharedMemorySize, DSMEM_REQ);
    cudaFuncSetAttribute(conv_mma<3>, cudaFuncAttributeMaxDynamicSharedMemorySize, DSMEM_REQ);
    cudaFuncSetAttribute(k_prep, cudaFuncAttributeMaxDynamicSharedMemorySize, 131072);

    k_zero<<<(1040 + 262144 + 255) / 256, 256>>>();
    k_packw<<<2304, 256>>>(w1, wpk);
    k_packw<<<2304, 256>>>(w2, wpk + WCONV);
    k_packw<<<2304, 256>>>(w3, wpk + 2 * WCONV);
    cudaMemcpyAsync(xm, x, (size_t)NE * 4, cudaMemcpyDeviceToDevice);
    k_prep<<<dim3(Hn, Bn), 256, 131072>>>(x, pa);

    dim3 grid(2, Hn / 2, Bn);
    conv_mma<1><<<grid, 256, DSMEM_REQ>>>(actA, wpk,             b1, xm, pa, actB, nullptr);
    conv_mma<1><<<grid, 256, DSMEM_REQ>>>(actB, wpk + WCONV,     b2, xm, pa, actA, nullptr);
    conv_mma<3><<<grid, 256, DSMEM_REQ>>>(actA, wpk + 2 * WCONV, b3, xm, pa, nullptr, out);
}